// round 4
// baseline (speedup 1.0000x reference)
#include <cuda_runtime.h>
#include <cuda_bf16.h>

// ht[b,d] = sum_{s=start}^{start+x-1} hidden[b,s,d]
// start = sum(mask[B-1, :]) - x   (JAX x64-disabled: mask & x are int32)
//
// Latency-optimized: every block SPECULATIVELY sums the window at
// guess = S - x (address depends only on the tiny x load, not the mask),
// while block 0 alone reduces the mask row and publishes the true start.
// After accumulating, blocks poll the published start; if it differs from
// the guess they redo the sum (correct for arbitrary masks; on full-length
// sessions the fast path always holds). Deterministic: block 0 recomputes
// and republishes the same value every call; a stale flag from a previous
// graph replay exposes an identical start value.

__device__ int          g_start;
__device__ volatile int g_flag;   // 0 -> not published yet (zero-init), 1 -> published

__global__ void __launch_bounds__(256)
srsmlp_window_sum_kernel(const float* __restrict__ hidden,
                         const int* __restrict__ mask,
                         const int* __restrict__ xptr,
                         float* __restrict__ out,
                         int B, int S, int D4, int chunks /* D4/16 */)
{
    const int tid = threadIdx.x;
    const int col = tid & 15;         // float4 column within 16-wide chunk
    const int sg  = tid >> 4;         // s-group 0..15
    const int b     = blockIdx.x / chunks;
    const int chunk = blockIdx.x - b * chunks;

    const int x     = __ldg(xptr);    // 4B load, first thing on the wire
    const int guess = S - x;          // speculative start

    // ---- speculative window accumulation (independent of the mask) ----
    const int d4 = (chunk << 4) + col;
    const float4* __restrict__ hid4 = reinterpret_cast<const float4*>(hidden);
    const float4* __restrict__ base =
        hid4 + ((long long)b * S + guess) * D4 + d4;

    float4 a0 = make_float4(0.f,0.f,0.f,0.f);
    float4 a1 = a0, a2 = a0, a3 = a0;

    int r = sg;
    for (; r + 48 < x; r += 64) {     // x=64: rows sg, +16, +32, +48
        float4 v0 = base[(long long)(r)      * D4];
        float4 v1 = base[(long long)(r + 16) * D4];
        float4 v2 = base[(long long)(r + 32) * D4];
        float4 v3 = base[(long long)(r + 48) * D4];
        a0.x += v0.x; a0.y += v0.y; a0.z += v0.z; a0.w += v0.w;
        a1.x += v1.x; a1.y += v1.y; a1.z += v1.z; a1.w += v1.w;
        a2.x += v2.x; a2.y += v2.y; a2.z += v2.z; a2.w += v2.w;
        a3.x += v3.x; a3.y += v3.y; a3.z += v3.z; a3.w += v3.w;
    }
    for (; r < x; r += 16) {
        float4 v = base[(long long)r * D4];
        a0.x += v.x; a0.y += v.y; a0.z += v.z; a0.w += v.w;
    }

    // ---- block 0: reduce mask row, publish true start ----
    __shared__ int s_len;
    __shared__ int s_start;
    if (blockIdx.x == 0) {
        if (tid == 0) s_len = 0;
        __syncthreads();
        const int* mrow = mask + (long long)(B - 1) * S;
        const int  S4   = S >> 2;
        const int4* mrow4 = reinterpret_cast<const int4*>(mrow);
        int acc = 0;
        for (int i = tid; i < S4; i += 256) {
            int4 v = mrow4[i];
            acc += v.x + v.y + v.z + v.w;
        }
        for (int i = (S4 << 2) + tid; i < S; i += 256)
            acc += mrow[i];
        #pragma unroll
        for (int off = 16; off > 0; off >>= 1)
            acc += __shfl_down_sync(0xFFFFFFFFu, acc, off);
        if ((tid & 31) == 0)
            atomicAdd(&s_len, acc);
        __syncthreads();
        if (tid == 0) {
            g_start = s_len - x;
            __threadfence();          // start visible before flag
            g_flag = 1;
            s_start = s_len - x;
        }
        __syncthreads();
    } else {
        if (tid == 0) {
            while (g_flag == 0) { }   // HW-backed L2 poll; set by block 0
            __threadfence();
            s_start = *(volatile int*)&g_start;
        }
        __syncthreads();
    }
    const int start = s_start;

    // ---- verify speculation; redo if the guess was wrong ----
    if (start != guess) {
        a0 = make_float4(0.f,0.f,0.f,0.f);
        a1 = a0; a2 = a0; a3 = a0;
        const float4* __restrict__ tbase =
            hid4 + ((long long)b * S + start) * D4 + d4;
        int rr = sg;
        for (; rr + 48 < x; rr += 64) {
            float4 v0 = tbase[(long long)(rr)      * D4];
            float4 v1 = tbase[(long long)(rr + 16) * D4];
            float4 v2 = tbase[(long long)(rr + 32) * D4];
            float4 v3 = tbase[(long long)(rr + 48) * D4];
            a0.x += v0.x; a0.y += v0.y; a0.z += v0.z; a0.w += v0.w;
            a1.x += v1.x; a1.y += v1.y; a1.z += v1.z; a1.w += v1.w;
            a2.x += v2.x; a2.y += v2.y; a2.z += v2.z; a2.w += v2.w;
            a3.x += v3.x; a3.y += v3.y; a3.z += v3.z; a3.w += v3.w;
        }
        for (; rr < x; rr += 16) {
            float4 v = tbase[(long long)rr * D4];
            a0.x += v.x; a0.y += v.y; a0.z += v.z; a0.w += v.w;
        }
    }

    a0.x += a1.x + a2.x + a3.x;
    a0.y += a1.y + a2.y + a3.y;
    a0.z += a1.z + a2.z + a3.z;
    a0.w += a1.w + a2.w + a3.w;

    // ---- reduce 16 s-groups in shared memory ----
    __shared__ float4 red[16][16];    // 4 KB
    red[sg][col] = a0;
    __syncthreads();

    if (tid < 16) {
        float4 t = red[0][tid];
        #pragma unroll
        for (int j = 1; j < 16; ++j) {
            float4 v = red[j][tid];
            t.x += v.x; t.y += v.y; t.z += v.z; t.w += v.w;
        }
        reinterpret_cast<float4*>(out)[(long long)b * D4 + d4] = t;
    }
}

extern "C" void kernel_launch(void* const* d_in, const int* in_sizes, int n_in,
                              void* d_out, int out_size)
{
    const float* hidden = (const float*)d_in[0];
    const int*   mask   = (const int*)d_in[1];
    const int*   xptr   = (const int*)d_in[2];
    float*       out    = (float*)d_out;

    const long long hidden_elems = in_sizes[0];
    const long long mask_elems   = in_sizes[1];

    const int D  = (int)(hidden_elems / mask_elems);  // 1024
    const int B  = out_size / D;                      // 32
    const int S  = (int)(mask_elems / B);             // 2048
    const int D4 = D >> 2;                            // 256
    const int chunks = D4 >> 4;                       // 16

    dim3 grid(B * chunks);                            // 512 blocks
    srsmlp_window_sum_kernel<<<grid, 256>>>(hidden, mask, xptr, out,
                                            B, S, D4, chunks);
}

// round 5
// speedup vs baseline: 1.3527x; 1.3527x over previous
#include <cuda_runtime.h>
#include <cuda_bf16.h>

// ht[b,d] = sum_{s=start}^{start+x-1} hidden[b,s,d]
// start = sum(mask[B-1, :]) - x   (JAX x64-disabled: mask & x are int32)
//
// Single-round latency design: speculative window loads for rows [S-64, S)
// are issued with NO load dependencies (compile-time guess x=64, full-length
// session), concurrently with the x load and this block's mask-row loads.
// After all loads land, if (x==64 && session_len==S) the speculative sum is
// used; otherwise a generic slow path recomputes (correct for any input).
// No cross-block communication, no polling.

__global__ void __launch_bounds__(256)
srsmlp_window_sum_kernel(const float* __restrict__ hidden,
                         const int* __restrict__ mask,
                         const int* __restrict__ xptr,
                         float* __restrict__ out,
                         int B, int S, int D4, int chunks /* D4/16 */)
{
    const int tid = threadIdx.x;
    const int col = tid & 15;         // float4 column within 16-wide chunk
    const int sg  = tid >> 4;         // s-group 0..15
    const int b     = blockIdx.x / chunks;
    const int chunk = blockIdx.x - b * chunks;

    const int d4 = (chunk << 4) + col;
    const float4* __restrict__ hid4 = reinterpret_cast<const float4*>(hidden);

    __shared__ int s_len;
    if (tid == 0) s_len = 0;

    // ---- issue ALL independent loads up front ----
    // (a) speculative window rows [S-64, S): no dependency on any load
    const bool can_spec = (S >= 64);
    const int  gs = S - 64;
    const float4* __restrict__ sbase =
        hid4 + ((long long)b * S + gs) * D4 + d4;
    float4 v0, v1, v2, v3;
    if (can_spec) {
        v0 = sbase[(long long)(sg)      * D4];
        v1 = sbase[(long long)(sg + 16) * D4];
        v2 = sbase[(long long)(sg + 32) * D4];
        v3 = sbase[(long long)(sg + 48) * D4];
    } else {
        v0 = v1 = v2 = v3 = make_float4(0.f,0.f,0.f,0.f);
    }

    // (b) scalar x
    const int x = __ldg(xptr);

    // (c) this block's copy of the mask row (8KB, L2-resident after wave 1)
    int macc = 0;
    {
        const int* mrow = mask + (long long)(B - 1) * S;
        const int  S4   = S >> 2;
        const int4* mrow4 = reinterpret_cast<const int4*>(mrow);
        for (int i = tid; i < S4; i += 256) {       // 2 int4 loads for S=2048
            int4 v = mrow4[i];
            macc += v.x + v.y + v.z + v.w;
        }
        for (int i = (S4 << 2) + tid; i < S; i += 256)
            macc += mrow[i];
    }
    __syncthreads();                  // s_len=0 visible

    // ---- reduce mask while window loads are still in flight ----
    #pragma unroll
    for (int off = 16; off > 0; off >>= 1)
        macc += __shfl_down_sync(0xFFFFFFFFu, macc, off);
    if ((tid & 31) == 0)
        atomicAdd(&s_len, macc);
    __syncthreads();

    const int len   = s_len;
    const int start = len - x;

    float4 a;
    if (can_spec && x == 64 && len == S) {
        // fast path: speculative window was exactly right
        a.x = (v0.x + v1.x) + (v2.x + v3.x);
        a.y = (v0.y + v1.y) + (v2.y + v3.y);
        a.z = (v0.z + v1.z) + (v2.z + v3.z);
        a.w = (v0.w + v1.w) + (v2.w + v3.w);
    } else {
        // generic slow path: any x, any start
        a = make_float4(0.f,0.f,0.f,0.f);
        const float4* __restrict__ tbase =
            hid4 + ((long long)b * S + start) * D4 + d4;
        for (int r = sg; r < x; r += 16) {
            float4 v = tbase[(long long)r * D4];
            a.x += v.x; a.y += v.y; a.z += v.z; a.w += v.w;
        }
    }

    // ---- reduce 16 s-groups in shared memory ----
    __shared__ float4 red[16][16];    // 4 KB
    red[sg][col] = a;
    __syncthreads();

    if (tid < 16) {
        float4 t = red[0][tid];
        #pragma unroll
        for (int j = 1; j < 16; ++j) {
            float4 v = red[j][tid];
            t.x += v.x; t.y += v.y; t.z += v.z; t.w += v.w;
        }
        reinterpret_cast<float4*>(out)[(long long)b * D4 + d4] = t;
    }
}

extern "C" void kernel_launch(void* const* d_in, const int* in_sizes, int n_in,
                              void* d_out, int out_size)
{
    const float* hidden = (const float*)d_in[0];
    const int*   mask   = (const int*)d_in[1];
    const int*   xptr   = (const int*)d_in[2];
    float*       out    = (float*)d_out;

    const long long hidden_elems = in_sizes[0];
    const long long mask_elems   = in_sizes[1];

    const int D  = (int)(hidden_elems / mask_elems);  // 1024
    const int B  = out_size / D;                      // 32
    const int S  = (int)(mask_elems / B);             // 2048
    const int D4 = D >> 2;                            // 256
    const int chunks = D4 >> 4;                       // 16

    dim3 grid(B * chunks);                            // 512 blocks
    srsmlp_window_sum_kernel<<<grid, 256>>>(hidden, mask, xptr, out,
                                            B, S, D4, chunks);
}